// round 11
// baseline (speedup 1.0000x reference)
#include <cuda_runtime.h>
#include <cuda_bf16.h>
#include <math.h>
#include <stdint.h>

#define Bb 2
#define Tt 2048
#define Cc 768
#define Hh 12
#define Dd 64
#define NBH (Bb*Hh)

// ---------------- scratch (device globals; no runtime allocation) ----------
__device__ float g_q[(size_t)NBH*Tt*Dd];
__device__ float g_k[(size_t)NBH*Tt*Dd];
__device__ float g_v[(size_t)NBH*Tt*Dd];
__device__ __nv_bfloat16 g_x_hi[(size_t)4096*768];
__device__ __nv_bfloat16 g_x_lo[(size_t)4096*768];
__device__ __nv_bfloat16 g_w_hi[(size_t)4*768*768];
__device__ __nv_bfloat16 g_w_lo[(size_t)4*768*768];
__device__ __nv_bfloat16 g_q_hi[(size_t)NBH*Tt*Dd];
__device__ __nv_bfloat16 g_q_lo[(size_t)NBH*Tt*Dd];
__device__ __nv_bfloat16 g_k_hi[(size_t)NBH*Tt*Dd];
__device__ __nv_bfloat16 g_k_lo[(size_t)NBH*Tt*Dd];
__device__ __nv_bfloat16 g_vT_hi[(size_t)NBH*Dd*Tt];
__device__ __nv_bfloat16 g_vT_lo[(size_t)NBH*Dd*Tt];
__device__ __nv_bfloat16 g_y_hi[(size_t)NBH*Tt*Dd];
__device__ __nv_bfloat16 g_y_lo[(size_t)NBH*Tt*Dd];
__device__ float g_y_p0[(size_t)NBH*Tt*Dd];
__device__ float g_y_p1[(size_t)NBH*Tt*Dd];
__device__ float g_rope[(size_t)Tt*64];

// ---------------- helpers ---------------------------------------------------
__device__ __forceinline__ uint32_t smem_u32(const void* p) {
    uint32_t a;
    asm("{ .reg .u64 t; cvta.to.shared.u64 t, %1; cvt.u32.u64 %0, t; }" : "=r"(a) : "l"(p));
    return a;
}
__device__ __forceinline__ void cpa16(uint32_t d, const void* s) {
    asm volatile("cp.async.cg.shared.global [%0], [%1], 16;" :: "r"(d), "l"(s));
}
__device__ __forceinline__ void cp_commit() { asm volatile("cp.async.commit_group;" ::: "memory"); }
__device__ __forceinline__ void cp_wait0()  { asm volatile("cp.async.wait_group 0;" ::: "memory"); }
__device__ __forceinline__ void cp_wait1()  { asm volatile("cp.async.wait_group 1;" ::: "memory"); }
__device__ __forceinline__ void ldmat4(uint32_t* r, uint32_t a) {
    asm volatile("ldmatrix.sync.aligned.m8n8.x4.shared.b16 {%0,%1,%2,%3}, [%4];"
                 : "=r"(r[0]), "=r"(r[1]), "=r"(r[2]), "=r"(r[3]) : "r"(a));
}
__device__ __forceinline__ void mma_bf16(float* c, const uint32_t* a, const uint32_t* b) {
    asm volatile("mma.sync.aligned.m16n8k16.row.col.f32.bf16.bf16.f32 "
                 "{%0,%1,%2,%3}, {%4,%5,%6,%7}, {%8,%9}, {%0,%1,%2,%3};"
                 : "+f"(c[0]), "+f"(c[1]), "+f"(c[2]), "+f"(c[3])
                 : "r"(a[0]), "r"(a[1]), "r"(a[2]), "r"(a[3]), "r"(b[0]), "r"(b[1]));
}
__device__ __forceinline__ uint32_t packbf2(float a, float b) {
    __nv_bfloat162 t = __floats2bfloat162_rn(a, b);
    return reinterpret_cast<uint32_t&>(t);
}
__device__ __forceinline__ void split2u(float a, float b, uint32_t& hi, uint32_t& lo) {
    float ah = __bfloat162float(__float2bfloat16(a));
    float bh = __bfloat162float(__float2bfloat16(b));
    hi = packbf2(ah, bh);
    lo = packbf2(a - ah, b - bh);
}
__device__ __forceinline__ void split4(float4 f, uint2& hi, uint2& lo) {
    split2u(f.x, f.y, hi.x, lo.x);
    split2u(f.z, f.w, hi.y, lo.y);
}

// cp.async issue: A-hi/A-lo/B-hi/B-lo tiles, 4x16B per plane per thread.
__device__ __forceinline__ void issue4(uint32_t dbase,
    const __nv_bfloat16* s0, const __nv_bfloat16* s1,
    const __nv_bfloat16* s2, const __nv_bfloat16* s3) {
    #pragma unroll
    for (int j = 0; j < 4; j++) {
        cpa16(dbase + 0u*18432u + j*16, s0 + j*8);
        cpa16(dbase + 1u*18432u + j*16, s1 + j*8);
        cpa16(dbase + 2u*18432u + j*16, s2 + j*8);
        cpa16(dbase + 3u*18432u + j*16, s3 + j*8);
    }
    cp_commit();
}

// one k=64 chunk, CTA tile 128x128, warp tile 64x32
__device__ __forceinline__ void consume_128x128(
    uint32_t AH, uint32_t AL, uint32_t BH, uint32_t BL,
    int wr, int wc, int lane, float (&acc)[4][4][4]) {
    #pragma unroll
    for (int half = 0; half < 2; half++) {
        uint32_t bh[4][4], bl[4][4];
        #pragma unroll
        for (int j = 0; j < 4; j++) {
            uint32_t off = (uint32_t)((wc*32 + j*8 + (lane & 7)) * 144 + half*64 + ((lane >> 3) & 3) * 16);
            ldmat4(bh[j], BH + off);
            ldmat4(bl[j], BL + off);
        }
        #pragma unroll
        for (int s = 0; s < 2; s++) {
            uint32_t ah[4][4], al[4][4];
            #pragma unroll
            for (int i = 0; i < 4; i++) {
                uint32_t off = (uint32_t)((wr*64 + i*16 + (lane & 15)) * 144 + half*64 + s*32 + (lane >> 4) * 16);
                ldmat4(ah[i], AH + off);
                ldmat4(al[i], AL + off);
            }
            #pragma unroll
            for (int i = 0; i < 4; i++)
                #pragma unroll
                for (int j = 0; j < 4; j++) {
                    mma_bf16(acc[i][j], ah[i], &bh[j][s*2]);
                    mma_bf16(acc[i][j], ah[i], &bl[j][s*2]);
                    mma_bf16(acc[i][j], al[i], &bh[j][s*2]);
                }
        }
    }
}

// one k=64 chunk, CTA tile 128x64, warp tile 64x16
__device__ __forceinline__ void consume_128x64(
    uint32_t AH, uint32_t AL, uint32_t BH, uint32_t BL,
    int wr, int wc, int lane, float (&acc)[4][2][4]) {
    #pragma unroll
    for (int half = 0; half < 2; half++) {
        uint32_t bh[2][4], bl[2][4];
        #pragma unroll
        for (int j = 0; j < 2; j++) {
            uint32_t off = (uint32_t)((wc*16 + j*8 + (lane & 7)) * 144 + half*64 + ((lane >> 3) & 3) * 16);
            ldmat4(bh[j], BH + off);
            ldmat4(bl[j], BL + off);
        }
        #pragma unroll
        for (int s = 0; s < 2; s++) {
            #pragma unroll
            for (int i = 0; i < 4; i++) {
                uint32_t ah[4], al[4];
                uint32_t off = (uint32_t)((wr*64 + i*16 + (lane & 15)) * 144 + half*64 + s*32 + (lane >> 4) * 16);
                ldmat4(ah, AH + off);
                ldmat4(al, AL + off);
                #pragma unroll
                for (int j = 0; j < 2; j++) {
                    mma_bf16(acc[i][j], ah, &bh[j][s*2]);
                    mma_bf16(acc[i][j], ah, &bl[j][s*2]);
                    mma_bf16(acc[i][j], al, &bh[j][s*2]);
                }
            }
        }
    }
}

#define GBUF 73728

// ---------------------------------------------------------------------------
// prep: split x and the 4 weight matrices into bf16 hi/lo planes (flat grid)
// ---------------------------------------------------------------------------
__global__ __launch_bounds__(256) void prep_kernel(
    const float* __restrict__ x, const float* __restrict__ Wq,
    const float* __restrict__ Wk, const float* __restrict__ Wv,
    const float* __restrict__ Wp)
{
    const int bid = blockIdx.x;
    const float* src;
    __nv_bfloat16 *dh, *dl;
    int i4;
    if (bid < 3072) {
        src = x; dh = g_x_hi; dl = g_x_lo;
        i4 = bid * 256 + threadIdx.x;
    } else {
        int r = bid - 3072;
        int y = r / 576;
        src = (y == 0) ? Wq : (y == 1) ? Wk : (y == 2) ? Wv : Wp;
        dh = g_w_hi + (size_t)y*589824;
        dl = g_w_lo + (size_t)y*589824;
        i4 = (r % 576) * 256 + threadIdx.x;
    }
    float4 f = ((const float4*)src)[i4];
    uint2 hi, lo;
    split4(f, hi, lo);
    ((uint2*)dh)[i4] = hi;
    ((uint2*)dl)[i4] = lo;
}

// ---------------------------------------------------------------------------
// QKV projection (tensor): out = x @ W^T, M=4096 N=768 K=768
// ---------------------------------------------------------------------------
__global__ __launch_bounds__(256, 1) void qkv_kernel()
{
    extern __shared__ char dsm[];
    const uint32_t sb = smem_u32(dsm);
    const int t = threadIdx.x, lane = t & 31, w = t >> 5, wr = w >> 2, wc = w & 3;
    const int m0 = blockIdx.y * 128, n0 = blockIdx.x * 128, z = blockIdx.z;
    float* out = (z == 0) ? g_q : (z == 1) ? g_k : g_v;

    const int row = t >> 1, hf = t & 1;
    const __nv_bfloat16* ah = g_x_hi + (size_t)(m0+row)*768 + hf*32;
    const __nv_bfloat16* al = g_x_lo + (size_t)(m0+row)*768 + hf*32;
    const __nv_bfloat16* bh = g_w_hi + (size_t)z*589824 + (size_t)(n0+row)*768 + hf*32;
    const __nv_bfloat16* bl = g_w_lo + (size_t)z*589824 + (size_t)(n0+row)*768 + hf*32;
    const uint32_t doff = (uint32_t)(row*144 + hf*64);

    float acc[4][4][4] = {};
    issue4(sb + doff, ah, al, bh, bl);
    for (int c = 0; c < 12; c++) {
        if (c + 1 < 12)
            issue4(sb + ((c+1)&1)*GBUF + doff, ah + (c+1)*64, al + (c+1)*64, bh + (c+1)*64, bl + (c+1)*64);
        if (c + 1 < 12) cp_wait1(); else cp_wait0();
        __syncthreads();
        uint32_t bb = sb + (c & 1)*GBUF;
        consume_128x128(bb, bb+18432, bb+36864, bb+55296, wr, wc, lane, acc);
        __syncthreads();
    }
    const int r0 = lane >> 2, cp2 = (lane & 3)*2;
    #pragma unroll
    for (int i = 0; i < 4; i++) {
        int m = m0 + wr*64 + i*16 + r0;
        int b = m >> 11, tt = m & (Tt-1);
        #pragma unroll
        for (int j = 0; j < 4; j++) {
            int n = n0 + wc*32 + j*8 + cp2;
            int h = n >> 6, d = n & 63;
            size_t base = (((size_t)(b*Hh + h))*Tt + tt)*Dd + d;
            *(float2*)&out[base]          = make_float2(acc[i][j][0], acc[i][j][1]);
            *(float2*)&out[base + 8*Dd]   = make_float2(acc[i][j][2], acc[i][j][3]);
        }
    }
}

// ---------------------------------------------------------------------------
// rope tables
// ---------------------------------------------------------------------------
__global__ __launch_bounds__(256) void rope_prep()
{
    int idx = blockIdx.x * 256 + threadIdx.x;
    if (idx >= Tt * 16) return;
    int t = idx >> 4, p = idx & 15;
    const float L2 = 0.41524101186092028f; // log2(10000)/32
    float f1 = exp2f(-(float)p * L2), f2 = exp2f(-(float)(p + 16) * L2);
    float s1, c1, s2, c2;
    sincosf((float)t * f1, &s1, &c1);
    sincosf((float)t * f2, &s2, &c2);
    float* r = g_rope + (size_t)t * 64;
    r[p] = c1; r[p + 16] = s1; r[p + 32] = c2; r[p + 48] = s2;
}

// ---------------------------------------------------------------------------
// rope: 8 threads/row, shfl pair exchange, coalesced. q,k fp32 -> hi/lo bf16
// ---------------------------------------------------------------------------
__global__ __launch_bounds__(256) void rope_kernel()
{
    const int gid = blockIdx.x * 256 + threadIdx.x;
    const int j = gid & 7;
    const int ri = gid >> 3;
    const int t = ri & (Tt - 1);
    const float* tab = g_rope + (size_t)t * 64;

    float vq[8], vk[8];
    *(float4*)&vq[0] = *(const float4*)(g_q + (size_t)ri*64 + j*8);
    *(float4*)&vq[4] = *(const float4*)(g_q + (size_t)ri*64 + j*8 + 4);
    *(float4*)&vk[0] = *(const float4*)(g_k + (size_t)ri*64 + j*8);
    *(float4*)&vk[4] = *(const float4*)(g_k + (size_t)ri*64 + j*8 + 4);

    float pq[8], pk[8];
    #pragma unroll
    for (int e = 0; e < 8; e++) {
        pq[e] = __shfl_xor_sync(0xffffffffu, vq[e], 2);
        pk[e] = __shfl_xor_sync(0xffffffffu, vk[e], 2);
    }
    if (j < 2) {
        #pragma unroll
        for (int e = 0; e < 8; e++) {
            int p = j*8 + e;
            float cs = tab[p], sn = tab[16 + p];
            vq[e] = vq[e]*cs - pq[e]*sn;
            vk[e] = vk[e]*cs - pk[e]*sn;
        }
    } else if (j < 4) {
        #pragma unroll
        for (int e = 0; e < 8; e++) {
            int p = j*8 + e;
            float cs = tab[p + 16], sn = tab[p + 32];
            vq[e] = vq[e]*cs + pq[e]*sn;
            vk[e] = vk[e]*cs + pk[e]*sn;
        }
    }
    uint2 h0, l0, h1, l1;
    split4(*(float4*)&vq[0], h0, l0);
    split4(*(float4*)&vq[4], h1, l1);
    *(uint4*)(g_q_hi + (size_t)ri*64 + j*8) = make_uint4(h0.x, h0.y, h1.x, h1.y);
    *(uint4*)(g_q_lo + (size_t)ri*64 + j*8) = make_uint4(l0.x, l0.y, l1.x, l1.y);
    split4(*(float4*)&vk[0], h0, l0);
    split4(*(float4*)&vk[4], h1, l1);
    *(uint4*)(g_k_hi + (size_t)ri*64 + j*8) = make_uint4(h0.x, h0.y, h1.x, h1.y);
    *(uint4*)(g_k_lo + (size_t)ri*64 + j*8) = make_uint4(l0.x, l0.y, l1.x, l1.y);
}

// ---------------------------------------------------------------------------
// v transpose + split: g_v[bh][t][d] -> g_vT_{hi,lo}[bh][d][t]
// ---------------------------------------------------------------------------
__global__ __launch_bounds__(256) void vT_kernel()
{
    __shared__ float tile[32][33];
    const int bh = blockIdx.z, t0 = blockIdx.x * 32, d0 = blockIdx.y * 32;
    const int tx = threadIdx.x & 31, ty = threadIdx.x >> 5;
    const float* src = g_v + ((size_t)bh * Tt + t0) * Dd + d0;
    #pragma unroll
    for (int r = 0; r < 32; r += 8) tile[ty + r][tx] = src[(size_t)(ty + r) * Dd + tx];
    __syncthreads();
    #pragma unroll
    for (int r = 0; r < 32; r += 8) {
        float v = tile[tx][ty + r];
        size_t o = ((size_t)bh * Dd + d0 + ty + r) * Tt + t0 + tx;
        __nv_bfloat16 h = __float2bfloat16(v);
        g_vT_hi[o] = h;
        g_vT_lo[o] = __float2bfloat16(v - __bfloat162float(h));
    }
}

// ---------------------------------------------------------------------------
// logits (tensor): att[m,n] = 0.125*q.k + rel_bias. occupancy 2, heavy-first.
// Computing CTAs with kt<qt ALSO zero-fill their mirror (upper-tri) tile
// during the MMA-bound phase (idle store pipe). kt>qt CTAs exit immediately.
// ---------------------------------------------------------------------------
__global__ __launch_bounds__(256, 2) void logits_kernel(
    const float* __restrict__ rel_bias, float* __restrict__ att)
{
    const int kt = blockIdx.x, qt = 15 - blockIdx.y, bh = blockIdx.z;
    if (kt > qt) return;
    extern __shared__ char dsm[];
    __shared__ float bias_s[256];
    const uint32_t sb = smem_u32(dsm);
    const int t = threadIdx.x, lane = t & 31, w = t >> 5, wr = w >> 2, wc = w & 3;
    const int h = bh % Hh;
    const int dlo = (qt - kt) * 128 - 127;
    for (int i = t; i < 255; i += 256)
        bias_s[i] = __ldg(&rel_bias[(size_t)(dlo + i + Tt - 1) * Hh + h]);

    const int row = t >> 1, hf = t & 1;
    issue4(sb + (uint32_t)(row*144 + hf*64),
           g_q_hi + ((size_t)bh*Tt + qt*128 + row)*Dd + hf*32,
           g_q_lo + ((size_t)bh*Tt + qt*128 + row)*Dd + hf*32,
           g_k_hi + ((size_t)bh*Tt + kt*128 + row)*Dd + hf*32,
           g_k_lo + ((size_t)bh*Tt + kt*128 + row)*Dd + hf*32);

    // mirror-tile zero-fill (strictly upper): rows kt*128.., cols qt*128..
    if (kt < qt) {
        float4* dst = (float4*)(att + (size_t)bh*Tt*Tt + ((size_t)kt*128 + row)*Tt + qt*128 + hf*64);
        const float4 z4 = make_float4(0.f, 0.f, 0.f, 0.f);
        #pragma unroll
        for (int g = 0; g < 16; g++) dst[g] = z4;
    }

    cp_wait0();
    __syncthreads();
    float acc[4][4][4] = {};
    consume_128x128(sb, sb+18432, sb+36864, sb+55296, wr, wc, lane, acc);

    const int r0 = lane >> 2, cp2 = (lane & 3)*2;
    float* A = att + (size_t)bh * Tt * Tt;
    #pragma unroll
    for (int i = 0; i < 4; i++) {
        int mi = wr*64 + i*16 + r0;
        #pragma unroll
        for (int j = 0; j < 4; j++) {
            int ni = wc*32 + j*8 + cp2;
            float b0 = bias_s[mi - ni + 127],      b1 = bias_s[mi - ni + 126];
            float b2 = bias_s[mi + 8 - ni + 127],  b3 = bias_s[mi + 8 - ni + 126];
            size_t base = ((size_t)qt*128 + mi)*Tt + kt*128 + ni;
            *(float2*)&A[base]        = make_float2(acc[i][j][0]*0.125f + b0, acc[i][j][1]*0.125f + b1);
            *(float2*)&A[base + 8*Tt] = make_float2(acc[i][j][2]*0.125f + b2, acc[i][j][3]*0.125f + b3);
        }
    }
}

// ---------------------------------------------------------------------------
// row softmax in place: reads/exps up to causal length; writes only up to the
// end of the diagonal tile (upper tiles pre-zeroed by logits mirror stores).
// ---------------------------------------------------------------------------
__global__ __launch_bounds__(256) void softmax_kernel(float* __restrict__ att)
{
    const int row = blockIdx.x;
    const int m = row & (Tt - 1);
    const int L = m + 1;
    const int nFull = L >> 2;
    const int rem = L & 3;
    const int nT4 = ((m >> 7) + 1) * 32;   // quads up to diagonal tile end
    float4* A = (float4*)(att + (size_t)row * Tt);
    __shared__ float4 buf[Tt/4];
    __shared__ float red[8];
    const int tid = threadIdx.x;
    const bool bnd = (rem != 0) && (tid == (nFull & 255));

    float mx = -1e30f;
    for (int j = tid; j < nFull; j += 256) {
        float4 v = A[j];
        buf[j] = v;
        mx = fmaxf(fmaxf(mx, fmaxf(v.x, v.y)), fmaxf(v.z, v.w));
    }
    if (bnd) {
        float4 v = A[nFull];
        if (rem < 2) v.y = -1e30f;
        if (rem < 3) v.z = -1e30f;
        v.w = -1e30f;
        buf[nFull] = v;
        mx = fmaxf(fmaxf(mx, fmaxf(v.x, v.y)), fmaxf(v.z, v.w));
    }
    #pragma unroll
    for (int o = 16; o; o >>= 1) mx = fmaxf(mx, __shfl_xor_sync(0xffffffffu, mx, o));
    if ((tid & 31) == 0) red[tid >> 5] = mx;
    __syncthreads();
    mx = red[0];
    #pragma unroll
    for (int ww = 1; ww < 8; ww++) mx = fmaxf(mx, red[ww]);
    __syncthreads();

    float s = 0.f;
    for (int j = tid; j < nFull; j += 256) {
        float4 v = buf[j];
        v.x = __expf(v.x - mx);
        v.y = __expf(v.y - mx);
        v.z = __expf(v.z - mx);
        v.w = __expf(v.w - mx);
        s += v.x + v.y + v.z + v.w;
        buf[j] = v;
    }
    if (bnd) {
        float4 v = buf[nFull];
        v.x = __expf(v.x - mx);
        v.y = (rem > 1) ? __expf(v.y - mx) : 0.f;
        v.z = (rem > 2) ? __expf(v.z - mx) : 0.f;
        v.w = 0.f;
        s += v.x + v.y + v.z;
        buf[nFull] = v;
    }
    #pragma unroll
    for (int o = 16; o; o >>= 1) s += __shfl_xor_sync(0xffffffffu, s, o);
    if ((tid & 31) == 0) red[tid >> 5] = s;
    __syncthreads();
    s = red[0];
    #pragma unroll
    for (int ww = 1; ww < 8; ww++) s += red[ww];
    const float inv = 1.f / s;

    for (int j = tid; j < nFull; j += 256) {
        float4 e = buf[j];
        e.x *= inv; e.y *= inv; e.z *= inv; e.w *= inv;
        A[j] = e;
    }
    if (bnd) {
        float4 e = buf[nFull];
        e.x *= inv; e.y *= inv; e.z *= inv;
        A[nFull] = e;
    }
    const int start = nFull + (rem ? 1 : 0);
    const float4 z4 = make_float4(0.f, 0.f, 0.f, 0.f);
    for (int j = start + tid; j < nT4; j += 256) A[j] = z4;
}

// ---------------------------------------------------------------------------
// av (tensor): y_part = att @ v over a K-half. blockIdx.z = K-split index.
// Writes fp32 partials; ycomb adds + splits to hi/lo.
// ---------------------------------------------------------------------------
#define AV2_B_BASE 73728u
#define AV2_SMEM   110592

__global__ __launch_bounds__(256, 2) void av_kernel(const float* __restrict__ att)
{
    extern __shared__ char dsm[];
    const uint32_t sb = smem_u32(dsm);
    const int mt = 15 - blockIdx.x, bh = blockIdx.y, ks = blockIdx.z;
    const int t = threadIdx.x, lane = t & 31, w = t >> 5, wr = w >> 2, wc = w & 3;
    const float* As = att + (size_t)bh * Tt * Tt;

    const int row = t >> 1, hf = t & 1;
    const int br = t >> 2, bq = t & 3;
    const int nk = (mt + 1) * 2;
    const int c0 = ks ? (mt + 1) : 0;
    const int c1 = ks ? nk : (mt + 1);

    float acc[4][2][4] = {};
    float4 ap[8];

    {
        const float* asrc = As + ((size_t)(mt*128 + row))*Tt + c0*64 + hf*32;
        #pragma unroll
        for (int i = 0; i < 8; i++) ap[i] = __ldg((const float4*)asrc + i);
        #pragma unroll
        for (int pl = 0; pl < 2; pl++) {
            const __nv_bfloat16* src = (pl ? g_vT_lo : g_vT_hi) + ((size_t)bh*Dd + br)*Tt + c0*64 + bq*16;
            uint32_t dst = sb + AV2_B_BASE + (c0 & 1)*18432u + pl*9216u + (uint32_t)(br*144 + bq*32);
            cpa16(dst, src);
            cpa16(dst + 16, src + 8);
        }
        cp_commit();
        char* th = dsm + (c0 & 1)*36864 + row*144 + hf*64;
        char* tl = th + 18432;
        #pragma unroll
        for (int g = 0; g < 4; g++) {
            uint2 h0, l0, h1, l1;
            split4(ap[2*g],   h0, l0);
            split4(ap[2*g+1], h1, l1);
            *(uint4*)(th + g*16) = make_uint4(h0.x, h0.y, h1.x, h1.y);
            *(uint4*)(tl + g*16) = make_uint4(l0.x, l0.y, l1.x, l1.y);
        }
    }

    for (int c = c0; c < c1; c++) {
        if (c + 1 < c1) {
            #pragma unroll
            for (int pl = 0; pl < 2; pl++) {
                const __nv_bfloat16* src = (pl ? g_vT_lo : g_vT_hi) + ((size_t)bh*Dd + br)*Tt + (c+1)*64 + bq*16;
                uint32_t dst = sb + AV2_B_BASE + ((c+1)&1)*18432u + pl*9216u + (uint32_t)(br*144 + bq*32);
                cpa16(dst, src);
                cpa16(dst + 16, src + 8);
            }
            cp_commit();
            const float* asrc = As + ((size_t)(mt*128 + row))*Tt + (c+1)*64 + hf*32;
            #pragma unroll
            for (int i = 0; i < 8; i++) ap[i] = __ldg((const float4*)asrc + i);
        }
        if (c + 1 < c1) cp_wait1(); else cp_wait0();
        __syncthreads();
        uint32_t abuf = sb + (c & 1)*36864u;
        uint32_t bbuf = sb + AV2_B_BASE + (c & 1)*18432u;
        consume_128x64(abuf, abuf + 18432, bbuf, bbuf + 9216, wr, wc, lane, acc);
        if (c + 1 < c1) {
            char* th = dsm + ((c+1)&1)*36864 + row*144 + hf*64;
            char* tl = th + 18432;
            #pragma unroll
            for (int g = 0; g < 4; g++) {
                uint2 h0, l0, h1, l1;
                split4(ap[2*g],   h0, l0);
                split4(ap[2*g+1], h1, l1);
                *(uint4*)(th + g*16) = make_uint4(h0.x, h0.y, h1.x, h1.y);
                *(uint4*)(tl + g*16) = make_uint4(l0.x, l0.y, l1.x, l1.y);
            }
        }
        __syncthreads();
    }

    float* yp = ks ? g_y_p1 : g_y_p0;
    const int r0 = lane >> 2, cp2 = (lane & 3)*2;
    #pragma unroll
    for (int i = 0; i < 4; i++) {
        int m = mt*128 + wr*64 + i*16 + r0;
        #pragma unroll
        for (int j = 0; j < 2; j++) {
            int n = wc*16 + j*8 + cp2;
            size_t idx = ((size_t)bh*Tt + m)*Dd + n;
            *(float2*)&yp[idx]        = make_float2(acc[i][j][0], acc[i][j][1]);
            *(float2*)&yp[idx + 8*Dd] = make_float2(acc[i][j][2], acc[i][j][3]);
        }
    }
}

// ---------------------------------------------------------------------------
// ycomb: y = p0 + p1, split to bf16 hi/lo planes
// ---------------------------------------------------------------------------
__global__ __launch_bounds__(256) void ycomb_kernel()
{
    size_t i4 = (size_t)blockIdx.x * 256 + threadIdx.x;
    float4 a = ((const float4*)g_y_p0)[i4];
    float4 b = ((const float4*)g_y_p1)[i4];
    a.x += b.x; a.y += b.y; a.z += b.z; a.w += b.w;
    uint2 hi, lo;
    split4(a, hi, lo);
    ((uint2*)g_y_hi)[i4] = hi;
    ((uint2*)g_y_lo)[i4] = lo;
}

// ---------------------------------------------------------------------------
// output projection (tensor): y = yatt @ Wp^T + bp, M=4096 N=768 K=768
// ---------------------------------------------------------------------------
__global__ __launch_bounds__(256, 1) void proj_kernel(
    const float* __restrict__ bp, float* __restrict__ y)
{
    extern __shared__ char dsm[];
    const uint32_t sb = smem_u32(dsm);
    const int t = threadIdx.x, lane = t & 31, w = t >> 5, wr = w >> 2, wc = w & 3;
    const int m0 = blockIdx.y * 128, n0 = blockIdx.x * 128;

    const int row = t >> 1, hf = t & 1;
    const int mrow = m0 + row, b_ = mrow >> 11, t_ = mrow & (Tt - 1);
    const __nv_bfloat16* bh = g_w_hi + (size_t)3*589824 + (size_t)(n0+row)*768 + hf*32;
    const __nv_bfloat16* bl = g_w_lo + (size_t)3*589824 + (size_t)(n0+row)*768 + hf*32;
    const uint32_t doff = (uint32_t)(row*144 + hf*64);

    float acc[4][4][4] = {};
    issue4(sb + doff,
           g_y_hi + (((size_t)(b_*Hh + 0))*Tt + t_)*Dd + hf*32,
           g_y_lo + (((size_t)(b_*Hh + 0))*Tt + t_)*Dd + hf*32,
           bh, bl);
    for (int c = 0; c < 12; c++) {
        if (c + 1 < 12)
            issue4(sb + ((c+1)&1)*GBUF + doff,
                   g_y_hi + (((size_t)(b_*Hh + c+1))*Tt + t_)*Dd + hf*32,
                   g_y_lo + (((size_t)(b_*Hh + c+1))*Tt + t_)*Dd + hf*32,
                   bh + (c+1)*64, bl + (c+1)*64);
        if (c + 1 < 12) cp_wait1(); else cp_wait0();
        __syncthreads();
        uint32_t bb = sb + (c & 1)*GBUF;
        consume_128x128(bb, bb+18432, bb+36864, bb+55296, wr, wc, lane, acc);
        __syncthreads();
    }
    const int r0 = lane >> 2, cp2 = (lane & 3)*2;
    #pragma unroll
    for (int i = 0; i < 4; i++) {
        int m = m0 + wr*64 + i*16 + r0;
        #pragma unroll
        for (int j = 0; j < 4; j++) {
            int n = n0 + wc*32 + j*8 + cp2;
            float2 bv = *(const float2*)&bp[n];
            *(float2*)&y[(size_t)m*Cc + n] =
                make_float2(acc[i][j][0] + bv.x, acc[i][j][1] + bv.y);
            *(float2*)&y[(size_t)(m+8)*Cc + n] =
                make_float2(acc[i][j][2] + bv.x, acc[i][j][3] + bv.y);
        }
    }
}

// ---------------------------------------------------------------------------
extern "C" void kernel_launch(void* const* d_in, const int* in_sizes, int n_in,
                              void* d_out, int out_size)
{
    (void)in_sizes; (void)n_in; (void)out_size;
    const float* x  = (const float*)d_in[0];
    const float* Wq = (const float*)d_in[1];
    const float* Wk = (const float*)d_in[2];
    const float* Wv = (const float*)d_in[3];
    const float* Wp = (const float*)d_in[4];
    const float* bp = (const float*)d_in[5];
    const float* rb = (const float*)d_in[6];
    float* y   = (float*)d_out;
    float* att = y + (size_t)Bb * Tt * Cc;

    static int inited = 0;
    if (!inited) {
        cudaFuncSetAttribute(qkv_kernel,    cudaFuncAttributeMaxDynamicSharedMemorySize, 2*GBUF);
        cudaFuncSetAttribute(logits_kernel, cudaFuncAttributeMaxDynamicSharedMemorySize, GBUF);
        cudaFuncSetAttribute(av_kernel,     cudaFuncAttributeMaxDynamicSharedMemorySize, AV2_SMEM);
        cudaFuncSetAttribute(proj_kernel,   cudaFuncAttributeMaxDynamicSharedMemorySize, 2*GBUF);
        inited = 1;
    }

    prep_kernel   <<<3072 + 4*576, 256>>>(x, Wq, Wk, Wv, Wp);
    qkv_kernel    <<<dim3(6, 32, 3), 256, 2*GBUF>>>();
    rope_prep     <<<128, 256>>>();
    rope_kernel   <<<NBH*Tt*8/256, 256>>>();
    vT_kernel     <<<dim3(64, 2, NBH), 256>>>();
    logits_kernel <<<dim3(16, 16, NBH), 256, GBUF>>>(rb, att);
    softmax_kernel<<<NBH*Tt, 256>>>(att);
    av_kernel     <<<dim3(16, NBH, 2), 256, AV2_SMEM>>>(att);
    ycomb_kernel  <<<NBH*Tt*Dd/1024, 256>>>();
    proj_kernel   <<<dim3(6, 32), 256, 2*GBUF>>>(bp, y);
}

// round 12
// speedup vs baseline: 1.0699x; 1.0699x over previous
#include <cuda_runtime.h>
#include <cuda_bf16.h>
#include <math.h>
#include <stdint.h>

#define Bb 2
#define Tt 2048
#define Cc 768
#define Hh 12
#define Dd 64
#define NBH (Bb*Hh)

// ---------------- scratch (device globals; no runtime allocation) ----------
__device__ float g_q[(size_t)NBH*Tt*Dd];
__device__ float g_k[(size_t)NBH*Tt*Dd];
__device__ float g_v[(size_t)NBH*Tt*Dd];
__device__ __nv_bfloat16 g_x_hi[(size_t)4096*768];
__device__ __nv_bfloat16 g_x_lo[(size_t)4096*768];
__device__ __nv_bfloat16 g_w_hi[(size_t)4*768*768];
__device__ __nv_bfloat16 g_w_lo[(size_t)4*768*768];
__device__ __nv_bfloat16 g_q_hi[(size_t)NBH*Tt*Dd];
__device__ __nv_bfloat16 g_q_lo[(size_t)NBH*Tt*Dd];
__device__ __nv_bfloat16 g_k_hi[(size_t)NBH*Tt*Dd];
__device__ __nv_bfloat16 g_k_lo[(size_t)NBH*Tt*Dd];
__device__ __nv_bfloat16 g_vT_hi[(size_t)NBH*Dd*Tt];
__device__ __nv_bfloat16 g_vT_lo[(size_t)NBH*Dd*Tt];
__device__ __nv_bfloat16 g_y_hi[(size_t)NBH*Tt*Dd];
__device__ __nv_bfloat16 g_y_lo[(size_t)NBH*Tt*Dd];
__device__ float g_y_p0[(size_t)NBH*Tt*Dd];
__device__ float g_y_p1[(size_t)NBH*Tt*Dd];
__device__ float g_rope[(size_t)Tt*64];

// ---------------- helpers ---------------------------------------------------
__device__ __forceinline__ uint32_t smem_u32(const void* p) {
    uint32_t a;
    asm("{ .reg .u64 t; cvta.to.shared.u64 t, %1; cvt.u32.u64 %0, t; }" : "=r"(a) : "l"(p));
    return a;
}
__device__ __forceinline__ void cpa16(uint32_t d, const void* s) {
    asm volatile("cp.async.cg.shared.global [%0], [%1], 16;" :: "r"(d), "l"(s));
}
__device__ __forceinline__ void cp_commit() { asm volatile("cp.async.commit_group;" ::: "memory"); }
__device__ __forceinline__ void cp_wait0()  { asm volatile("cp.async.wait_group 0;" ::: "memory"); }
__device__ __forceinline__ void cp_wait1()  { asm volatile("cp.async.wait_group 1;" ::: "memory"); }
__device__ __forceinline__ void ldmat4(uint32_t* r, uint32_t a) {
    asm volatile("ldmatrix.sync.aligned.m8n8.x4.shared.b16 {%0,%1,%2,%3}, [%4];"
                 : "=r"(r[0]), "=r"(r[1]), "=r"(r[2]), "=r"(r[3]) : "r"(a));
}
__device__ __forceinline__ void mma_bf16(float* c, const uint32_t* a, const uint32_t* b) {
    asm volatile("mma.sync.aligned.m16n8k16.row.col.f32.bf16.bf16.f32 "
                 "{%0,%1,%2,%3}, {%4,%5,%6,%7}, {%8,%9}, {%0,%1,%2,%3};"
                 : "+f"(c[0]), "+f"(c[1]), "+f"(c[2]), "+f"(c[3])
                 : "r"(a[0]), "r"(a[1]), "r"(a[2]), "r"(a[3]), "r"(b[0]), "r"(b[1]));
}
__device__ __forceinline__ uint32_t packbf2(float a, float b) {
    __nv_bfloat162 t = __floats2bfloat162_rn(a, b);
    return reinterpret_cast<uint32_t&>(t);
}
__device__ __forceinline__ void split2u(float a, float b, uint32_t& hi, uint32_t& lo) {
    float ah = __bfloat162float(__float2bfloat16(a));
    float bh = __bfloat162float(__float2bfloat16(b));
    hi = packbf2(ah, bh);
    lo = packbf2(a - ah, b - bh);
}
__device__ __forceinline__ void split4(float4 f, uint2& hi, uint2& lo) {
    split2u(f.x, f.y, hi.x, lo.x);
    split2u(f.z, f.w, hi.y, lo.y);
}

// cp.async issue: A-hi/A-lo/B-hi/B-lo tiles, 4x16B per plane per thread.
__device__ __forceinline__ void issue4(uint32_t dbase,
    const __nv_bfloat16* s0, const __nv_bfloat16* s1,
    const __nv_bfloat16* s2, const __nv_bfloat16* s3) {
    #pragma unroll
    for (int j = 0; j < 4; j++) {
        cpa16(dbase + 0u*18432u + j*16, s0 + j*8);
        cpa16(dbase + 1u*18432u + j*16, s1 + j*8);
        cpa16(dbase + 2u*18432u + j*16, s2 + j*8);
        cpa16(dbase + 3u*18432u + j*16, s3 + j*8);
    }
    cp_commit();
}

// one k=64 chunk, CTA tile 128x128, warp tile 64x32
__device__ __forceinline__ void consume_128x128(
    uint32_t AH, uint32_t AL, uint32_t BH, uint32_t BL,
    int wr, int wc, int lane, float (&acc)[4][4][4]) {
    #pragma unroll
    for (int half = 0; half < 2; half++) {
        uint32_t bh[4][4], bl[4][4];
        #pragma unroll
        for (int j = 0; j < 4; j++) {
            uint32_t off = (uint32_t)((wc*32 + j*8 + (lane & 7)) * 144 + half*64 + ((lane >> 3) & 3) * 16);
            ldmat4(bh[j], BH + off);
            ldmat4(bl[j], BL + off);
        }
        #pragma unroll
        for (int s = 0; s < 2; s++) {
            uint32_t ah[4][4], al[4][4];
            #pragma unroll
            for (int i = 0; i < 4; i++) {
                uint32_t off = (uint32_t)((wr*64 + i*16 + (lane & 15)) * 144 + half*64 + s*32 + (lane >> 4) * 16);
                ldmat4(ah[i], AH + off);
                ldmat4(al[i], AL + off);
            }
            #pragma unroll
            for (int i = 0; i < 4; i++)
                #pragma unroll
                for (int j = 0; j < 4; j++) {
                    mma_bf16(acc[i][j], ah[i], &bh[j][s*2]);
                    mma_bf16(acc[i][j], ah[i], &bl[j][s*2]);
                    mma_bf16(acc[i][j], al[i], &bh[j][s*2]);
                }
        }
    }
}

// one k=64 chunk, CTA tile 128x64, warp tile 64x16
__device__ __forceinline__ void consume_128x64(
    uint32_t AH, uint32_t AL, uint32_t BH, uint32_t BL,
    int wr, int wc, int lane, float (&acc)[4][2][4]) {
    #pragma unroll
    for (int half = 0; half < 2; half++) {
        uint32_t bh[2][4], bl[2][4];
        #pragma unroll
        for (int j = 0; j < 2; j++) {
            uint32_t off = (uint32_t)((wc*16 + j*8 + (lane & 7)) * 144 + half*64 + ((lane >> 3) & 3) * 16);
            ldmat4(bh[j], BH + off);
            ldmat4(bl[j], BL + off);
        }
        #pragma unroll
        for (int s = 0; s < 2; s++) {
            #pragma unroll
            for (int i = 0; i < 4; i++) {
                uint32_t ah[4], al[4];
                uint32_t off = (uint32_t)((wr*64 + i*16 + (lane & 15)) * 144 + half*64 + s*32 + (lane >> 4) * 16);
                ldmat4(ah, AH + off);
                ldmat4(al, AL + off);
                #pragma unroll
                for (int j = 0; j < 2; j++) {
                    mma_bf16(acc[i][j], ah, &bh[j][s*2]);
                    mma_bf16(acc[i][j], ah, &bl[j][s*2]);
                    mma_bf16(acc[i][j], al, &bh[j][s*2]);
                }
            }
        }
    }
}

#define GBUF 73728

// ---------------------------------------------------------------------------
// prep: split x and the 4 weight matrices into bf16 hi/lo planes (flat grid)
// ---------------------------------------------------------------------------
__global__ __launch_bounds__(256) void prep_kernel(
    const float* __restrict__ x, const float* __restrict__ Wq,
    const float* __restrict__ Wk, const float* __restrict__ Wv,
    const float* __restrict__ Wp)
{
    const int bid = blockIdx.x;
    const float* src;
    __nv_bfloat16 *dh, *dl;
    int i4;
    if (bid < 3072) {
        src = x; dh = g_x_hi; dl = g_x_lo;
        i4 = bid * 256 + threadIdx.x;
    } else {
        int r = bid - 3072;
        int y = r / 576;
        src = (y == 0) ? Wq : (y == 1) ? Wk : (y == 2) ? Wv : Wp;
        dh = g_w_hi + (size_t)y*589824;
        dl = g_w_lo + (size_t)y*589824;
        i4 = (r % 576) * 256 + threadIdx.x;
    }
    float4 f = ((const float4*)src)[i4];
    uint2 hi, lo;
    split4(f, hi, lo);
    ((uint2*)dh)[i4] = hi;
    ((uint2*)dl)[i4] = lo;
}

// ---------------------------------------------------------------------------
// QKV projection (tensor): out = x @ W^T, M=4096 N=768 K=768.
// Single-buffered smem, occupancy 2 (cross-CTA overlap hides load latency).
// ---------------------------------------------------------------------------
__global__ __launch_bounds__(256, 2) void qkv_kernel()
{
    extern __shared__ char dsm[];
    const uint32_t sb = smem_u32(dsm);
    const int t = threadIdx.x, lane = t & 31, w = t >> 5, wr = w >> 2, wc = w & 3;
    const int m0 = blockIdx.y * 128, n0 = blockIdx.x * 128, z = blockIdx.z;
    float* out = (z == 0) ? g_q : (z == 1) ? g_k : g_v;

    const int row = t >> 1, hf = t & 1;
    const __nv_bfloat16* ah = g_x_hi + (size_t)(m0+row)*768 + hf*32;
    const __nv_bfloat16* al = g_x_lo + (size_t)(m0+row)*768 + hf*32;
    const __nv_bfloat16* bh = g_w_hi + (size_t)z*589824 + (size_t)(n0+row)*768 + hf*32;
    const __nv_bfloat16* bl = g_w_lo + (size_t)z*589824 + (size_t)(n0+row)*768 + hf*32;
    const uint32_t doff = (uint32_t)(row*144 + hf*64);

    float acc[4][4][4] = {};
    for (int c = 0; c < 12; c++) {
        issue4(sb + doff, ah + c*64, al + c*64, bh + c*64, bl + c*64);
        cp_wait0();
        __syncthreads();
        consume_128x128(sb, sb+18432, sb+36864, sb+55296, wr, wc, lane, acc);
        __syncthreads();
    }
    const int r0 = lane >> 2, cp2 = (lane & 3)*2;
    #pragma unroll
    for (int i = 0; i < 4; i++) {
        int m = m0 + wr*64 + i*16 + r0;
        int b = m >> 11, tt = m & (Tt-1);
        #pragma unroll
        for (int j = 0; j < 4; j++) {
            int n = n0 + wc*32 + j*8 + cp2;
            int h = n >> 6, d = n & 63;
            size_t base = (((size_t)(b*Hh + h))*Tt + tt)*Dd + d;
            *(float2*)&out[base]          = make_float2(acc[i][j][0], acc[i][j][1]);
            *(float2*)&out[base + 8*Dd]   = make_float2(acc[i][j][2], acc[i][j][3]);
        }
    }
}

// ---------------------------------------------------------------------------
// rope tables
// ---------------------------------------------------------------------------
__global__ __launch_bounds__(256) void rope_prep()
{
    int idx = blockIdx.x * 256 + threadIdx.x;
    if (idx >= Tt * 16) return;
    int t = idx >> 4, p = idx & 15;
    const float L2 = 0.41524101186092028f; // log2(10000)/32
    float f1 = exp2f(-(float)p * L2), f2 = exp2f(-(float)(p + 16) * L2);
    float s1, c1, s2, c2;
    sincosf((float)t * f1, &s1, &c1);
    sincosf((float)t * f2, &s2, &c2);
    float* r = g_rope + (size_t)t * 64;
    r[p] = c1; r[p + 16] = s1; r[p + 32] = c2; r[p + 48] = s2;
}

// ---------------------------------------------------------------------------
// rope: 8 threads/row, shfl pair exchange, coalesced. q,k fp32 -> hi/lo bf16
// ---------------------------------------------------------------------------
__global__ __launch_bounds__(256) void rope_kernel()
{
    const int gid = blockIdx.x * 256 + threadIdx.x;
    const int j = gid & 7;
    const int ri = gid >> 3;
    const int t = ri & (Tt - 1);
    const float* tab = g_rope + (size_t)t * 64;

    float vq[8], vk[8];
    *(float4*)&vq[0] = *(const float4*)(g_q + (size_t)ri*64 + j*8);
    *(float4*)&vq[4] = *(const float4*)(g_q + (size_t)ri*64 + j*8 + 4);
    *(float4*)&vk[0] = *(const float4*)(g_k + (size_t)ri*64 + j*8);
    *(float4*)&vk[4] = *(const float4*)(g_k + (size_t)ri*64 + j*8 + 4);

    float pq[8], pk[8];
    #pragma unroll
    for (int e = 0; e < 8; e++) {
        pq[e] = __shfl_xor_sync(0xffffffffu, vq[e], 2);
        pk[e] = __shfl_xor_sync(0xffffffffu, vk[e], 2);
    }
    if (j < 2) {
        #pragma unroll
        for (int e = 0; e < 8; e++) {
            int p = j*8 + e;
            float cs = tab[p], sn = tab[16 + p];
            vq[e] = vq[e]*cs - pq[e]*sn;
            vk[e] = vk[e]*cs - pk[e]*sn;
        }
    } else if (j < 4) {
        #pragma unroll
        for (int e = 0; e < 8; e++) {
            int p = j*8 + e;
            float cs = tab[p + 16], sn = tab[p + 32];
            vq[e] = vq[e]*cs + pq[e]*sn;
            vk[e] = vk[e]*cs + pk[e]*sn;
        }
    }
    uint2 h0, l0, h1, l1;
    split4(*(float4*)&vq[0], h0, l0);
    split4(*(float4*)&vq[4], h1, l1);
    *(uint4*)(g_q_hi + (size_t)ri*64 + j*8) = make_uint4(h0.x, h0.y, h1.x, h1.y);
    *(uint4*)(g_q_lo + (size_t)ri*64 + j*8) = make_uint4(l0.x, l0.y, l1.x, l1.y);
    split4(*(float4*)&vk[0], h0, l0);
    split4(*(float4*)&vk[4], h1, l1);
    *(uint4*)(g_k_hi + (size_t)ri*64 + j*8) = make_uint4(h0.x, h0.y, h1.x, h1.y);
    *(uint4*)(g_k_lo + (size_t)ri*64 + j*8) = make_uint4(l0.x, l0.y, l1.x, l1.y);
}

// ---------------------------------------------------------------------------
// v transpose + split: g_v[bh][t][d] -> g_vT_{hi,lo}[bh][d][t]
// ---------------------------------------------------------------------------
__global__ __launch_bounds__(256) void vT_kernel()
{
    __shared__ float tile[32][33];
    const int bh = blockIdx.z, t0 = blockIdx.x * 32, d0 = blockIdx.y * 32;
    const int tx = threadIdx.x & 31, ty = threadIdx.x >> 5;
    const float* src = g_v + ((size_t)bh * Tt + t0) * Dd + d0;
    #pragma unroll
    for (int r = 0; r < 32; r += 8) tile[ty + r][tx] = src[(size_t)(ty + r) * Dd + tx];
    __syncthreads();
    #pragma unroll
    for (int r = 0; r < 32; r += 8) {
        float v = tile[tx][ty + r];
        size_t o = ((size_t)bh * Dd + d0 + ty + r) * Tt + t0 + tx;
        __nv_bfloat16 h = __float2bfloat16(v);
        g_vT_hi[o] = h;
        g_vT_lo[o] = __float2bfloat16(v - __bfloat162float(h));
    }
}

// ---------------------------------------------------------------------------
// logits (tensor): att[m,n] = 0.125*q.k + rel_bias. occupancy 2, heavy-first.
// ---------------------------------------------------------------------------
__global__ __launch_bounds__(256, 2) void logits_kernel(
    const float* __restrict__ rel_bias, float* __restrict__ att)
{
    const int kt = blockIdx.x, qt = 15 - blockIdx.y, bh = blockIdx.z;
    if (kt > qt) return;
    extern __shared__ char dsm[];
    __shared__ float bias_s[256];
    const uint32_t sb = smem_u32(dsm);
    const int t = threadIdx.x, lane = t & 31, w = t >> 5, wr = w >> 2, wc = w & 3;
    const int h = bh % Hh;
    const int dlo = (qt - kt) * 128 - 127;
    for (int i = t; i < 255; i += 256)
        bias_s[i] = __ldg(&rel_bias[(size_t)(dlo + i + Tt - 1) * Hh + h]);

    const int row = t >> 1, hf = t & 1;
    issue4(sb + (uint32_t)(row*144 + hf*64),
           g_q_hi + ((size_t)bh*Tt + qt*128 + row)*Dd + hf*32,
           g_q_lo + ((size_t)bh*Tt + qt*128 + row)*Dd + hf*32,
           g_k_hi + ((size_t)bh*Tt + kt*128 + row)*Dd + hf*32,
           g_k_lo + ((size_t)bh*Tt + kt*128 + row)*Dd + hf*32);
    cp_wait0();
    __syncthreads();
    float acc[4][4][4] = {};
    consume_128x128(sb, sb+18432, sb+36864, sb+55296, wr, wc, lane, acc);

    const int r0 = lane >> 2, cp2 = (lane & 3)*2;
    float* A = att + (size_t)bh * Tt * Tt;
    #pragma unroll
    for (int i = 0; i < 4; i++) {
        int mi = wr*64 + i*16 + r0;
        #pragma unroll
        for (int j = 0; j < 4; j++) {
            int ni = wc*32 + j*8 + cp2;
            float b0 = bias_s[mi - ni + 127],      b1 = bias_s[mi - ni + 126];
            float b2 = bias_s[mi + 8 - ni + 127],  b3 = bias_s[mi + 8 - ni + 126];
            size_t base = ((size_t)qt*128 + mi)*Tt + kt*128 + ni;
            *(float2*)&A[base]        = make_float2(acc[i][j][0]*0.125f + b0, acc[i][j][1]*0.125f + b1);
            *(float2*)&A[base + 8*Tt] = make_float2(acc[i][j][2]*0.125f + b2, acc[i][j][3]*0.125f + b3);
        }
    }
}

// ---------------------------------------------------------------------------
// row softmax in place: reads/exps only up to causal length, zero tail to Tt.
// ---------------------------------------------------------------------------
__global__ __launch_bounds__(256) void softmax_kernel(float* __restrict__ att)
{
    const int row = blockIdx.x;
    const int m = row & (Tt - 1);
    const int L = m + 1;
    const int nFull = L >> 2;
    const int rem = L & 3;
    float4* A = (float4*)(att + (size_t)row * Tt);
    __shared__ float4 buf[Tt/4];
    __shared__ float red[8];
    const int tid = threadIdx.x;
    const bool bnd = (rem != 0) && (tid == (nFull & 255));

    float mx = -1e30f;
    for (int j = tid; j < nFull; j += 256) {
        float4 v = A[j];
        buf[j] = v;
        mx = fmaxf(fmaxf(mx, fmaxf(v.x, v.y)), fmaxf(v.z, v.w));
    }
    if (bnd) {
        float4 v = A[nFull];
        if (rem < 2) v.y = -1e30f;
        if (rem < 3) v.z = -1e30f;
        v.w = -1e30f;
        buf[nFull] = v;
        mx = fmaxf(fmaxf(mx, fmaxf(v.x, v.y)), fmaxf(v.z, v.w));
    }
    #pragma unroll
    for (int o = 16; o; o >>= 1) mx = fmaxf(mx, __shfl_xor_sync(0xffffffffu, mx, o));
    if ((tid & 31) == 0) red[tid >> 5] = mx;
    __syncthreads();
    mx = red[0];
    #pragma unroll
    for (int ww = 1; ww < 8; ww++) mx = fmaxf(mx, red[ww]);
    __syncthreads();

    float s = 0.f;
    for (int j = tid; j < nFull; j += 256) {
        float4 v = buf[j];
        v.x = __expf(v.x - mx);
        v.y = __expf(v.y - mx);
        v.z = __expf(v.z - mx);
        v.w = __expf(v.w - mx);
        s += v.x + v.y + v.z + v.w;
        buf[j] = v;
    }
    if (bnd) {
        float4 v = buf[nFull];
        v.x = __expf(v.x - mx);
        v.y = (rem > 1) ? __expf(v.y - mx) : 0.f;
        v.z = (rem > 2) ? __expf(v.z - mx) : 0.f;
        v.w = 0.f;
        s += v.x + v.y + v.z;
        buf[nFull] = v;
    }
    #pragma unroll
    for (int o = 16; o; o >>= 1) s += __shfl_xor_sync(0xffffffffu, s, o);
    if ((tid & 31) == 0) red[tid >> 5] = s;
    __syncthreads();
    s = red[0];
    #pragma unroll
    for (int ww = 1; ww < 8; ww++) s += red[ww];
    const float inv = 1.f / s;

    for (int j = tid; j < nFull; j += 256) {
        float4 e = buf[j];
        e.x *= inv; e.y *= inv; e.z *= inv; e.w *= inv;
        A[j] = e;
    }
    if (bnd) {
        float4 e = buf[nFull];
        e.x *= inv; e.y *= inv; e.z *= inv;
        A[nFull] = e;
    }
    const int start = nFull + (rem ? 1 : 0);
    const float4 z4 = make_float4(0.f, 0.f, 0.f, 0.f);
    for (int j = start + tid; j < Tt/4; j += 256) A[j] = z4;
}

// ---------------------------------------------------------------------------
// av (tensor): y_part = att @ v over a K-half. blockIdx.z = K-split index.
// Writes fp32 partials; ycomb adds + splits to hi/lo.
// ---------------------------------------------------------------------------
#define AV2_B_BASE 73728u
#define AV2_SMEM   110592

__global__ __launch_bounds__(256, 2) void av_kernel(const float* __restrict__ att)
{
    extern __shared__ char dsm[];
    const uint32_t sb = smem_u32(dsm);
    const int mt = 15 - blockIdx.x, bh = blockIdx.y, ks = blockIdx.z;
    const int t = threadIdx.x, lane = t & 31, w = t >> 5, wr = w >> 2, wc = w & 3;
    const float* As = att + (size_t)bh * Tt * Tt;

    const int row = t >> 1, hf = t & 1;
    const int br = t >> 2, bq = t & 3;
    const int nk = (mt + 1) * 2;
    const int c0 = ks ? (mt + 1) : 0;
    const int c1 = ks ? nk : (mt + 1);

    float acc[4][2][4] = {};
    float4 ap[8];

    {
        const float* asrc = As + ((size_t)(mt*128 + row))*Tt + c0*64 + hf*32;
        #pragma unroll
        for (int i = 0; i < 8; i++) ap[i] = __ldg((const float4*)asrc + i);
        #pragma unroll
        for (int pl = 0; pl < 2; pl++) {
            const __nv_bfloat16* src = (pl ? g_vT_lo : g_vT_hi) + ((size_t)bh*Dd + br)*Tt + c0*64 + bq*16;
            uint32_t dst = sb + AV2_B_BASE + (c0 & 1)*18432u + pl*9216u + (uint32_t)(br*144 + bq*32);
            cpa16(dst, src);
            cpa16(dst + 16, src + 8);
        }
        cp_commit();
        char* th = dsm + (c0 & 1)*36864 + row*144 + hf*64;
        char* tl = th + 18432;
        #pragma unroll
        for (int g = 0; g < 4; g++) {
            uint2 h0, l0, h1, l1;
            split4(ap[2*g],   h0, l0);
            split4(ap[2*g+1], h1, l1);
            *(uint4*)(th + g*16) = make_uint4(h0.x, h0.y, h1.x, h1.y);
            *(uint4*)(tl + g*16) = make_uint4(l0.x, l0.y, l1.x, l1.y);
        }
    }

    for (int c = c0; c < c1; c++) {
        if (c + 1 < c1) {
            #pragma unroll
            for (int pl = 0; pl < 2; pl++) {
                const __nv_bfloat16* src = (pl ? g_vT_lo : g_vT_hi) + ((size_t)bh*Dd + br)*Tt + (c+1)*64 + bq*16;
                uint32_t dst = sb + AV2_B_BASE + ((c+1)&1)*18432u + pl*9216u + (uint32_t)(br*144 + bq*32);
                cpa16(dst, src);
                cpa16(dst + 16, src + 8);
            }
            cp_commit();
            const float* asrc = As + ((size_t)(mt*128 + row))*Tt + (c+1)*64 + hf*32;
            #pragma unroll
            for (int i = 0; i < 8; i++) ap[i] = __ldg((const float4*)asrc + i);
        }
        if (c + 1 < c1) cp_wait1(); else cp_wait0();
        __syncthreads();
        uint32_t abuf = sb + (c & 1)*36864u;
        uint32_t bbuf = sb + AV2_B_BASE + (c & 1)*18432u;
        consume_128x64(abuf, abuf + 18432, bbuf, bbuf + 9216, wr, wc, lane, acc);
        if (c + 1 < c1) {
            char* th = dsm + ((c+1)&1)*36864 + row*144 + hf*64;
            char* tl = th + 18432;
            #pragma unroll
            for (int g = 0; g < 4; g++) {
                uint2 h0, l0, h1, l1;
                split4(ap[2*g],   h0, l0);
                split4(ap[2*g+1], h1, l1);
                *(uint4*)(th + g*16) = make_uint4(h0.x, h0.y, h1.x, h1.y);
                *(uint4*)(tl + g*16) = make_uint4(l0.x, l0.y, l1.x, l1.y);
            }
        }
        __syncthreads();
    }

    float* yp = ks ? g_y_p1 : g_y_p0;
    const int r0 = lane >> 2, cp2 = (lane & 3)*2;
    #pragma unroll
    for (int i = 0; i < 4; i++) {
        int m = mt*128 + wr*64 + i*16 + r0;
        #pragma unroll
        for (int j = 0; j < 2; j++) {
            int n = wc*16 + j*8 + cp2;
            size_t idx = ((size_t)bh*Tt + m)*Dd + n;
            *(float2*)&yp[idx]        = make_float2(acc[i][j][0], acc[i][j][1]);
            *(float2*)&yp[idx + 8*Dd] = make_float2(acc[i][j][2], acc[i][j][3]);
        }
    }
}

// ---------------------------------------------------------------------------
// ycomb: y = p0 + p1, split to bf16 hi/lo planes
// ---------------------------------------------------------------------------
__global__ __launch_bounds__(256) void ycomb_kernel()
{
    size_t i4 = (size_t)blockIdx.x * 256 + threadIdx.x;
    float4 a = ((const float4*)g_y_p0)[i4];
    float4 b = ((const float4*)g_y_p1)[i4];
    a.x += b.x; a.y += b.y; a.z += b.z; a.w += b.w;
    uint2 hi, lo;
    split4(a, hi, lo);
    ((uint2*)g_y_hi)[i4] = hi;
    ((uint2*)g_y_lo)[i4] = lo;
}

// ---------------------------------------------------------------------------
// output projection (tensor): y = yatt @ Wp^T + bp.
// Single-buffered smem, occupancy 2 (192 CTAs -> one wave of 296 slots).
// ---------------------------------------------------------------------------
__global__ __launch_bounds__(256, 2) void proj_kernel(
    const float* __restrict__ bp, float* __restrict__ y)
{
    extern __shared__ char dsm[];
    const uint32_t sb = smem_u32(dsm);
    const int t = threadIdx.x, lane = t & 31, w = t >> 5, wr = w >> 2, wc = w & 3;
    const int m0 = blockIdx.y * 128, n0 = blockIdx.x * 128;

    const int row = t >> 1, hf = t & 1;
    const int mrow = m0 + row, b_ = mrow >> 11, t_ = mrow & (Tt - 1);
    const __nv_bfloat16* bh = g_w_hi + (size_t)3*589824 + (size_t)(n0+row)*768 + hf*32;
    const __nv_bfloat16* bl = g_w_lo + (size_t)3*589824 + (size_t)(n0+row)*768 + hf*32;
    const uint32_t doff = (uint32_t)(row*144 + hf*64);

    float acc[4][4][4] = {};
    for (int c = 0; c < 12; c++) {
        issue4(sb + doff,
               g_y_hi + (((size_t)(b_*Hh + c))*Tt + t_)*Dd + hf*32,
               g_y_lo + (((size_t)(b_*Hh + c))*Tt + t_)*Dd + hf*32,
               bh + c*64, bl + c*64);
        cp_wait0();
        __syncthreads();
        consume_128x128(sb, sb+18432, sb+36864, sb+55296, wr, wc, lane, acc);
        __syncthreads();
    }
    const int r0 = lane >> 2, cp2 = (lane & 3)*2;
    #pragma unroll
    for (int i = 0; i < 4; i++) {
        int m = m0 + wr*64 + i*16 + r0;
        #pragma unroll
        for (int j = 0; j < 4; j++) {
            int n = n0 + wc*32 + j*8 + cp2;
            float2 bv = *(const float2*)&bp[n];
            *(float2*)&y[(size_t)m*Cc + n] =
                make_float2(acc[i][j][0] + bv.x, acc[i][j][1] + bv.y);
            *(float2*)&y[(size_t)(m+8)*Cc + n] =
                make_float2(acc[i][j][2] + bv.x, acc[i][j][3] + bv.y);
        }
    }
}

// ---------------------------------------------------------------------------
extern "C" void kernel_launch(void* const* d_in, const int* in_sizes, int n_in,
                              void* d_out, int out_size)
{
    (void)in_sizes; (void)n_in; (void)out_size;
    const float* x  = (const float*)d_in[0];
    const float* Wq = (const float*)d_in[1];
    const float* Wk = (const float*)d_in[2];
    const float* Wv = (const float*)d_in[3];
    const float* Wp = (const float*)d_in[4];
    const float* bp = (const float*)d_in[5];
    const float* rb = (const float*)d_in[6];
    float* y   = (float*)d_out;
    float* att = y + (size_t)Bb * Tt * Cc;

    static int inited = 0;
    if (!inited) {
        cudaFuncSetAttribute(qkv_kernel,    cudaFuncAttributeMaxDynamicSharedMemorySize, GBUF);
        cudaFuncSetAttribute(logits_kernel, cudaFuncAttributeMaxDynamicSharedMemorySize, GBUF);
        cudaFuncSetAttribute(av_kernel,     cudaFuncAttributeMaxDynamicSharedMemorySize, AV2_SMEM);
        cudaFuncSetAttribute(proj_kernel,   cudaFuncAttributeMaxDynamicSharedMemorySize, GBUF);
        inited = 1;
    }

    prep_kernel   <<<3072 + 4*576, 256>>>(x, Wq, Wk, Wv, Wp);
    qkv_kernel    <<<dim3(6, 32, 3), 256, GBUF>>>();
    rope_prep     <<<128, 256>>>();
    rope_kernel   <<<NBH*Tt*8/256, 256>>>();
    vT_kernel     <<<dim3(64, 2, NBH), 256>>>();
    logits_kernel <<<dim3(16, 16, NBH), 256, GBUF>>>(rb, att);
    softmax_kernel<<<NBH*Tt, 256>>>(att);
    av_kernel     <<<dim3(16, NBH, 2), 256, AV2_SMEM>>>(att);
    ycomb_kernel  <<<NBH*Tt*Dd/1024, 256>>>();
    proj_kernel   <<<dim3(6, 32), 256, GBUF>>>(bp, y);
}

// round 13
// speedup vs baseline: 1.1211x; 1.0478x over previous
#include <cuda_runtime.h>
#include <cuda_bf16.h>
#include <math.h>
#include <stdint.h>

#define Bb 2
#define Tt 2048
#define Cc 768
#define Hh 12
#define Dd 64
#define NBH (Bb*Hh)

// ---------------- scratch (device globals; no runtime allocation) ----------
__device__ float g_q[(size_t)NBH*Tt*Dd];
__device__ float g_k[(size_t)NBH*Tt*Dd];
__device__ float g_v[(size_t)NBH*Tt*Dd];
__device__ __nv_bfloat16 g_x_hi[(size_t)4096*768];
__device__ __nv_bfloat16 g_x_lo[(size_t)4096*768];
__device__ __nv_bfloat16 g_w_hi[(size_t)4*768*768];
__device__ __nv_bfloat16 g_w_lo[(size_t)4*768*768];
__device__ __nv_bfloat16 g_q_hi[(size_t)NBH*Tt*Dd];
__device__ __nv_bfloat16 g_q_lo[(size_t)NBH*Tt*Dd];
__device__ __nv_bfloat16 g_k_hi[(size_t)NBH*Tt*Dd];
__device__ __nv_bfloat16 g_k_lo[(size_t)NBH*Tt*Dd];
__device__ __nv_bfloat16 g_vT_hi[(size_t)NBH*Dd*Tt];
__device__ __nv_bfloat16 g_vT_lo[(size_t)NBH*Dd*Tt];
__device__ __nv_bfloat16 g_y_hi[(size_t)NBH*Tt*Dd];
__device__ __nv_bfloat16 g_y_lo[(size_t)NBH*Tt*Dd];
__device__ float g_y_p0[(size_t)NBH*Tt*Dd];
__device__ float g_y_p1[(size_t)NBH*Tt*Dd];
__device__ float g_rope[(size_t)Tt*64];

// ---------------- helpers ---------------------------------------------------
__device__ __forceinline__ uint32_t smem_u32(const void* p) {
    uint32_t a;
    asm("{ .reg .u64 t; cvta.to.shared.u64 t, %1; cvt.u32.u64 %0, t; }" : "=r"(a) : "l"(p));
    return a;
}
__device__ __forceinline__ void cpa16(uint32_t d, const void* s) {
    asm volatile("cp.async.cg.shared.global [%0], [%1], 16;" :: "r"(d), "l"(s));
}
__device__ __forceinline__ void cp_commit() { asm volatile("cp.async.commit_group;" ::: "memory"); }
__device__ __forceinline__ void cp_wait0()  { asm volatile("cp.async.wait_group 0;" ::: "memory"); }
__device__ __forceinline__ void ldmat4(uint32_t* r, uint32_t a) {
    asm volatile("ldmatrix.sync.aligned.m8n8.x4.shared.b16 {%0,%1,%2,%3}, [%4];"
                 : "=r"(r[0]), "=r"(r[1]), "=r"(r[2]), "=r"(r[3]) : "r"(a));
}
__device__ __forceinline__ void mma_bf16(float* c, const uint32_t* a, const uint32_t* b) {
    asm volatile("mma.sync.aligned.m16n8k16.row.col.f32.bf16.bf16.f32 "
                 "{%0,%1,%2,%3}, {%4,%5,%6,%7}, {%8,%9}, {%0,%1,%2,%3};"
                 : "+f"(c[0]), "+f"(c[1]), "+f"(c[2]), "+f"(c[3])
                 : "r"(a[0]), "r"(a[1]), "r"(a[2]), "r"(a[3]), "r"(b[0]), "r"(b[1]));
}
__device__ __forceinline__ uint32_t packbf2(float a, float b) {
    __nv_bfloat162 t = __floats2bfloat162_rn(a, b);
    return reinterpret_cast<uint32_t&>(t);
}
__device__ __forceinline__ void split2u(float a, float b, uint32_t& hi, uint32_t& lo) {
    float ah = __bfloat162float(__float2bfloat16(a));
    float bh = __bfloat162float(__float2bfloat16(b));
    hi = packbf2(ah, bh);
    lo = packbf2(a - ah, b - bh);
}
__device__ __forceinline__ void split4(float4 f, uint2& hi, uint2& lo) {
    split2u(f.x, f.y, hi.x, lo.x);
    split2u(f.z, f.w, hi.y, lo.y);
}

// cp.async issue: A-hi/A-lo/B-hi/B-lo tiles, 4x16B per plane per thread.
__device__ __forceinline__ void issue4(uint32_t dbase,
    const __nv_bfloat16* s0, const __nv_bfloat16* s1,
    const __nv_bfloat16* s2, const __nv_bfloat16* s3) {
    #pragma unroll
    for (int j = 0; j < 4; j++) {
        cpa16(dbase + 0u*18432u + j*16, s0 + j*8);
        cpa16(dbase + 1u*18432u + j*16, s1 + j*8);
        cpa16(dbase + 2u*18432u + j*16, s2 + j*8);
        cpa16(dbase + 3u*18432u + j*16, s3 + j*8);
    }
    cp_commit();
}

// one k=64 chunk, CTA tile 128x128, warp tile 64x32
__device__ __forceinline__ void consume_128x128(
    uint32_t AH, uint32_t AL, uint32_t BH, uint32_t BL,
    int wr, int wc, int lane, float (&acc)[4][4][4]) {
    #pragma unroll
    for (int half = 0; half < 2; half++) {
        uint32_t bh[4][4], bl[4][4];
        #pragma unroll
        for (int j = 0; j < 4; j++) {
            uint32_t off = (uint32_t)((wc*32 + j*8 + (lane & 7)) * 144 + half*64 + ((lane >> 3) & 3) * 16);
            ldmat4(bh[j], BH + off);
            ldmat4(bl[j], BL + off);
        }
        #pragma unroll
        for (int s = 0; s < 2; s++) {
            uint32_t ah[4][4], al[4][4];
            #pragma unroll
            for (int i = 0; i < 4; i++) {
                uint32_t off = (uint32_t)((wr*64 + i*16 + (lane & 15)) * 144 + half*64 + s*32 + (lane >> 4) * 16);
                ldmat4(ah[i], AH + off);
                ldmat4(al[i], AL + off);
            }
            #pragma unroll
            for (int i = 0; i < 4; i++)
                #pragma unroll
                for (int j = 0; j < 4; j++) {
                    mma_bf16(acc[i][j], ah[i], &bh[j][s*2]);
                    mma_bf16(acc[i][j], ah[i], &bl[j][s*2]);
                    mma_bf16(acc[i][j], al[i], &bh[j][s*2]);
                }
        }
    }
}

// one k=64 chunk, CTA tile 128x64, warp tile 64x16
__device__ __forceinline__ void consume_128x64(
    uint32_t AH, uint32_t AL, uint32_t BH, uint32_t BL,
    int wr, int wc, int lane, float (&acc)[4][2][4]) {
    #pragma unroll
    for (int half = 0; half < 2; half++) {
        uint32_t bh[2][4], bl[2][4];
        #pragma unroll
        for (int j = 0; j < 2; j++) {
            uint32_t off = (uint32_t)((wc*16 + j*8 + (lane & 7)) * 144 + half*64 + ((lane >> 3) & 3) * 16);
            ldmat4(bh[j], BH + off);
            ldmat4(bl[j], BL + off);
        }
        #pragma unroll
        for (int s = 0; s < 2; s++) {
            #pragma unroll
            for (int i = 0; i < 4; i++) {
                uint32_t ah[4], al[4];
                uint32_t off = (uint32_t)((wr*64 + i*16 + (lane & 15)) * 144 + half*64 + s*32 + (lane >> 4) * 16);
                ldmat4(ah, AH + off);
                ldmat4(al, AL + off);
                #pragma unroll
                for (int j = 0; j < 2; j++) {
                    mma_bf16(acc[i][j], ah, &bh[j][s*2]);
                    mma_bf16(acc[i][j], ah, &bl[j][s*2]);
                    mma_bf16(acc[i][j], al, &bh[j][s*2]);
                }
            }
        }
    }
}

#define GBUF 73728

// ---------------------------------------------------------------------------
// prep: split x and the 4 weight matrices into bf16 hi/lo planes (flat grid)
// ---------------------------------------------------------------------------
__global__ __launch_bounds__(256) void prep_kernel(
    const float* __restrict__ x, const float* __restrict__ Wq,
    const float* __restrict__ Wk, const float* __restrict__ Wv,
    const float* __restrict__ Wp)
{
    const int bid = blockIdx.x;
    const float* src;
    __nv_bfloat16 *dh, *dl;
    int i4;
    if (bid < 3072) {
        src = x; dh = g_x_hi; dl = g_x_lo;
        i4 = bid * 256 + threadIdx.x;
    } else {
        int r = bid - 3072;
        int y = r / 576;
        src = (y == 0) ? Wq : (y == 1) ? Wk : (y == 2) ? Wv : Wp;
        dh = g_w_hi + (size_t)y*589824;
        dl = g_w_lo + (size_t)y*589824;
        i4 = (r % 576) * 256 + threadIdx.x;
    }
    float4 f = ((const float4*)src)[i4];
    uint2 hi, lo;
    split4(f, hi, lo);
    ((uint2*)dh)[i4] = hi;
    ((uint2*)dl)[i4] = lo;
}

// ---------------------------------------------------------------------------
// QKV projection (tensor): out = x @ W^T, M=4096 N=768 K=768.
// Single-buffered smem, occupancy 2.
// ---------------------------------------------------------------------------
__global__ __launch_bounds__(256, 2) void qkv_kernel()
{
    extern __shared__ char dsm[];
    const uint32_t sb = smem_u32(dsm);
    const int t = threadIdx.x, lane = t & 31, w = t >> 5, wr = w >> 2, wc = w & 3;
    const int m0 = blockIdx.y * 128, n0 = blockIdx.x * 128, z = blockIdx.z;
    float* out = (z == 0) ? g_q : (z == 1) ? g_k : g_v;

    const int row = t >> 1, hf = t & 1;
    const __nv_bfloat16* ah = g_x_hi + (size_t)(m0+row)*768 + hf*32;
    const __nv_bfloat16* al = g_x_lo + (size_t)(m0+row)*768 + hf*32;
    const __nv_bfloat16* bh = g_w_hi + (size_t)z*589824 + (size_t)(n0+row)*768 + hf*32;
    const __nv_bfloat16* bl = g_w_lo + (size_t)z*589824 + (size_t)(n0+row)*768 + hf*32;
    const uint32_t doff = (uint32_t)(row*144 + hf*64);

    float acc[4][4][4] = {};
    for (int c = 0; c < 12; c++) {
        issue4(sb + doff, ah + c*64, al + c*64, bh + c*64, bl + c*64);
        cp_wait0();
        __syncthreads();
        consume_128x128(sb, sb+18432, sb+36864, sb+55296, wr, wc, lane, acc);
        __syncthreads();
    }
    const int r0 = lane >> 2, cp2 = (lane & 3)*2;
    #pragma unroll
    for (int i = 0; i < 4; i++) {
        int m = m0 + wr*64 + i*16 + r0;
        int b = m >> 11, tt = m & (Tt-1);
        #pragma unroll
        for (int j = 0; j < 4; j++) {
            int n = n0 + wc*32 + j*8 + cp2;
            int h = n >> 6, d = n & 63;
            size_t base = (((size_t)(b*Hh + h))*Tt + tt)*Dd + d;
            *(float2*)&out[base]          = make_float2(acc[i][j][0], acc[i][j][1]);
            *(float2*)&out[base + 8*Dd]   = make_float2(acc[i][j][2], acc[i][j][3]);
        }
    }
}

// ---------------------------------------------------------------------------
// rope tables
// ---------------------------------------------------------------------------
__global__ __launch_bounds__(256) void rope_prep()
{
    int idx = blockIdx.x * 256 + threadIdx.x;
    if (idx >= Tt * 16) return;
    int t = idx >> 4, p = idx & 15;
    const float L2 = 0.41524101186092028f; // log2(10000)/32
    float f1 = exp2f(-(float)p * L2), f2 = exp2f(-(float)(p + 16) * L2);
    float s1, c1, s2, c2;
    sincosf((float)t * f1, &s1, &c1);
    sincosf((float)t * f2, &s2, &c2);
    float* r = g_rope + (size_t)t * 64;
    r[p] = c1; r[p + 16] = s1; r[p + 32] = c2; r[p + 48] = s2;
}

// ---------------------------------------------------------------------------
// rope: 8 threads/row, shfl pair exchange, coalesced. q,k fp32 -> hi/lo bf16
// ---------------------------------------------------------------------------
__global__ __launch_bounds__(256) void rope_kernel()
{
    const int gid = blockIdx.x * 256 + threadIdx.x;
    const int j = gid & 7;
    const int ri = gid >> 3;
    const int t = ri & (Tt - 1);
    const float* tab = g_rope + (size_t)t * 64;

    float vq[8], vk[8];
    *(float4*)&vq[0] = *(const float4*)(g_q + (size_t)ri*64 + j*8);
    *(float4*)&vq[4] = *(const float4*)(g_q + (size_t)ri*64 + j*8 + 4);
    *(float4*)&vk[0] = *(const float4*)(g_k + (size_t)ri*64 + j*8);
    *(float4*)&vk[4] = *(const float4*)(g_k + (size_t)ri*64 + j*8 + 4);

    float pq[8], pk[8];
    #pragma unroll
    for (int e = 0; e < 8; e++) {
        pq[e] = __shfl_xor_sync(0xffffffffu, vq[e], 2);
        pk[e] = __shfl_xor_sync(0xffffffffu, vk[e], 2);
    }
    if (j < 2) {
        #pragma unroll
        for (int e = 0; e < 8; e++) {
            int p = j*8 + e;
            float cs = tab[p], sn = tab[16 + p];
            vq[e] = vq[e]*cs - pq[e]*sn;
            vk[e] = vk[e]*cs - pk[e]*sn;
        }
    } else if (j < 4) {
        #pragma unroll
        for (int e = 0; e < 8; e++) {
            int p = j*8 + e;
            float cs = tab[p + 16], sn = tab[p + 32];
            vq[e] = vq[e]*cs + pq[e]*sn;
            vk[e] = vk[e]*cs + pk[e]*sn;
        }
    }
    uint2 h0, l0, h1, l1;
    split4(*(float4*)&vq[0], h0, l0);
    split4(*(float4*)&vq[4], h1, l1);
    *(uint4*)(g_q_hi + (size_t)ri*64 + j*8) = make_uint4(h0.x, h0.y, h1.x, h1.y);
    *(uint4*)(g_q_lo + (size_t)ri*64 + j*8) = make_uint4(l0.x, l0.y, l1.x, l1.y);
    split4(*(float4*)&vk[0], h0, l0);
    split4(*(float4*)&vk[4], h1, l1);
    *(uint4*)(g_k_hi + (size_t)ri*64 + j*8) = make_uint4(h0.x, h0.y, h1.x, h1.y);
    *(uint4*)(g_k_lo + (size_t)ri*64 + j*8) = make_uint4(l0.x, l0.y, l1.x, l1.y);
}

// ---------------------------------------------------------------------------
// v transpose + split: g_v[bh][t][d] -> g_vT_{hi,lo}[bh][d][t]
// ---------------------------------------------------------------------------
__global__ __launch_bounds__(256) void vT_kernel()
{
    __shared__ float tile[32][33];
    const int bh = blockIdx.z, t0 = blockIdx.x * 32, d0 = blockIdx.y * 32;
    const int tx = threadIdx.x & 31, ty = threadIdx.x >> 5;
    const float* src = g_v + ((size_t)bh * Tt + t0) * Dd + d0;
    #pragma unroll
    for (int r = 0; r < 32; r += 8) tile[ty + r][tx] = src[(size_t)(ty + r) * Dd + tx];
    __syncthreads();
    #pragma unroll
    for (int r = 0; r < 32; r += 8) {
        float v = tile[tx][ty + r];
        size_t o = ((size_t)bh * Dd + d0 + ty + r) * Tt + t0 + tx;
        __nv_bfloat16 h = __float2bfloat16(v);
        g_vT_hi[o] = h;
        g_vT_lo[o] = __float2bfloat16(v - __bfloat162float(h));
    }
}

// ---------------------------------------------------------------------------
// logits (tensor): att[m,n] = 0.125*q.k + rel_bias. occupancy 2, heavy-first.
// ---------------------------------------------------------------------------
__global__ __launch_bounds__(256, 2) void logits_kernel(
    const float* __restrict__ rel_bias, float* __restrict__ att)
{
    const int kt = blockIdx.x, qt = 15 - blockIdx.y, bh = blockIdx.z;
    if (kt > qt) return;
    extern __shared__ char dsm[];
    __shared__ float bias_s[256];
    const uint32_t sb = smem_u32(dsm);
    const int t = threadIdx.x, lane = t & 31, w = t >> 5, wr = w >> 2, wc = w & 3;
    const int h = bh % Hh;
    const int dlo = (qt - kt) * 128 - 127;
    for (int i = t; i < 255; i += 256)
        bias_s[i] = __ldg(&rel_bias[(size_t)(dlo + i + Tt - 1) * Hh + h]);

    const int row = t >> 1, hf = t & 1;
    issue4(sb + (uint32_t)(row*144 + hf*64),
           g_q_hi + ((size_t)bh*Tt + qt*128 + row)*Dd + hf*32,
           g_q_lo + ((size_t)bh*Tt + qt*128 + row)*Dd + hf*32,
           g_k_hi + ((size_t)bh*Tt + kt*128 + row)*Dd + hf*32,
           g_k_lo + ((size_t)bh*Tt + kt*128 + row)*Dd + hf*32);
    cp_wait0();
    __syncthreads();
    float acc[4][4][4] = {};
    consume_128x128(sb, sb+18432, sb+36864, sb+55296, wr, wc, lane, acc);

    const int r0 = lane >> 2, cp2 = (lane & 3)*2;
    float* A = att + (size_t)bh * Tt * Tt;
    #pragma unroll
    for (int i = 0; i < 4; i++) {
        int mi = wr*64 + i*16 + r0;
        #pragma unroll
        for (int j = 0; j < 4; j++) {
            int ni = wc*32 + j*8 + cp2;
            float b0 = bias_s[mi - ni + 127],      b1 = bias_s[mi - ni + 126];
            float b2 = bias_s[mi + 8 - ni + 127],  b3 = bias_s[mi + 8 - ni + 126];
            size_t base = ((size_t)qt*128 + mi)*Tt + kt*128 + ni;
            *(float2*)&A[base]        = make_float2(acc[i][j][0]*0.125f + b0, acc[i][j][1]*0.125f + b1);
            *(float2*)&A[base + 8*Tt] = make_float2(acc[i][j][2]*0.125f + b2, acc[i][j][3]*0.125f + b3);
        }
    }
}

// ---------------------------------------------------------------------------
// row softmax in place: reads/exps only up to causal length, zero tail to Tt.
// ---------------------------------------------------------------------------
__global__ __launch_bounds__(256) void softmax_kernel(float* __restrict__ att)
{
    const int row = blockIdx.x;
    const int m = row & (Tt - 1);
    const int L = m + 1;
    const int nFull = L >> 2;
    const int rem = L & 3;
    float4* A = (float4*)(att + (size_t)row * Tt);
    __shared__ float4 buf[Tt/4];
    __shared__ float red[8];
    const int tid = threadIdx.x;
    const bool bnd = (rem != 0) && (tid == (nFull & 255));

    float mx = -1e30f;
    for (int j = tid; j < nFull; j += 256) {
        float4 v = A[j];
        buf[j] = v;
        mx = fmaxf(fmaxf(mx, fmaxf(v.x, v.y)), fmaxf(v.z, v.w));
    }
    if (bnd) {
        float4 v = A[nFull];
        if (rem < 2) v.y = -1e30f;
        if (rem < 3) v.z = -1e30f;
        v.w = -1e30f;
        buf[nFull] = v;
        mx = fmaxf(fmaxf(mx, fmaxf(v.x, v.y)), fmaxf(v.z, v.w));
    }
    #pragma unroll
    for (int o = 16; o; o >>= 1) mx = fmaxf(mx, __shfl_xor_sync(0xffffffffu, mx, o));
    if ((tid & 31) == 0) red[tid >> 5] = mx;
    __syncthreads();
    mx = red[0];
    #pragma unroll
    for (int ww = 1; ww < 8; ww++) mx = fmaxf(mx, red[ww]);
    __syncthreads();

    float s = 0.f;
    for (int j = tid; j < nFull; j += 256) {
        float4 v = buf[j];
        v.x = __expf(v.x - mx);
        v.y = __expf(v.y - mx);
        v.z = __expf(v.z - mx);
        v.w = __expf(v.w - mx);
        s += v.x + v.y + v.z + v.w;
        buf[j] = v;
    }
    if (bnd) {
        float4 v = buf[nFull];
        v.x = __expf(v.x - mx);
        v.y = (rem > 1) ? __expf(v.y - mx) : 0.f;
        v.z = (rem > 2) ? __expf(v.z - mx) : 0.f;
        v.w = 0.f;
        s += v.x + v.y + v.z;
        buf[nFull] = v;
    }
    #pragma unroll
    for (int o = 16; o; o >>= 1) s += __shfl_xor_sync(0xffffffffu, s, o);
    if ((tid & 31) == 0) red[tid >> 5] = s;
    __syncthreads();
    s = red[0];
    #pragma unroll
    for (int ww = 1; ww < 8; ww++) s += red[ww];
    const float inv = 1.f / s;

    for (int j = tid; j < nFull; j += 256) {
        float4 e = buf[j];
        e.x *= inv; e.y *= inv; e.z *= inv; e.w *= inv;
        A[j] = e;
    }
    if (bnd) {
        float4 e = buf[nFull];
        e.x *= inv; e.y *= inv; e.z *= inv;
        A[nFull] = e;
    }
    const int start = nFull + (rem ? 1 : 0);
    const float4 z4 = make_float4(0.f, 0.f, 0.f, 0.f);
    for (int j = start + tid; j < Tt/4; j += 256) A[j] = z4;
}

// ---------------------------------------------------------------------------
// av (tensor): y_part = att @ v over a K-half. Single-buffered smem,
// occupancy 3. A chunk via LDG->regs->split->STS, B via cp.async.
// smem: A hi/lo 36864 + B hi/lo 18432 = 55296.
// ---------------------------------------------------------------------------
#define AV3_B_BASE 36864u
#define AV3_SMEM   55296

__global__ __launch_bounds__(256, 3) void av_kernel(const float* __restrict__ att)
{
    extern __shared__ char dsm[];
    const uint32_t sb = smem_u32(dsm);
    const int mt = 15 - blockIdx.x, bh = blockIdx.y, ks = blockIdx.z;
    const int t = threadIdx.x, lane = t & 31, w = t >> 5, wr = w >> 2, wc = w & 3;
    const float* As = att + (size_t)bh * Tt * Tt;

    const int row = t >> 1, hf = t & 1;
    const int br = t >> 2, bq = t & 3;
    const int nk = (mt + 1) * 2;
    const int c0 = ks ? (mt + 1) : 0;
    const int c1 = ks ? nk : (mt + 1);

    float acc[4][2][4] = {};

    for (int c = c0; c < c1; c++) {
        // A chunk -> regs
        float4 ap[8];
        const float* asrc = As + ((size_t)(mt*128 + row))*Tt + c*64 + hf*32;
        #pragma unroll
        for (int i = 0; i < 8; i++) ap[i] = __ldg((const float4*)asrc + i);
        // B chunk -> cp.async
        #pragma unroll
        for (int pl = 0; pl < 2; pl++) {
            const __nv_bfloat16* src = (pl ? g_vT_lo : g_vT_hi) + ((size_t)bh*Dd + br)*Tt + c*64 + bq*16;
            uint32_t dst = sb + AV3_B_BASE + pl*9216u + (uint32_t)(br*144 + bq*32);
            cpa16(dst, src);
            cpa16(dst + 16, src + 8);
        }
        cp_commit();
        // split A regs -> smem tiles (previous consume finished at loop-end sync)
        {
            char* th = dsm + row*144 + hf*64;
            char* tl = th + 18432;
            #pragma unroll
            for (int g = 0; g < 4; g++) {
                uint2 h0, l0, h1, l1;
                split4(ap[2*g],   h0, l0);
                split4(ap[2*g+1], h1, l1);
                *(uint4*)(th + g*16) = make_uint4(h0.x, h0.y, h1.x, h1.y);
                *(uint4*)(tl + g*16) = make_uint4(l0.x, l0.y, l1.x, l1.y);
            }
        }
        cp_wait0();
        __syncthreads();
        consume_128x64(sb, sb + 18432, sb + AV3_B_BASE, sb + AV3_B_BASE + 9216, wr, wc, lane, acc);
        __syncthreads();
    }

    float* yp = ks ? g_y_p1 : g_y_p0;
    const int r0 = lane >> 2, cp2 = (lane & 3)*2;
    #pragma unroll
    for (int i = 0; i < 4; i++) {
        int m = mt*128 + wr*64 + i*16 + r0;
        #pragma unroll
        for (int j = 0; j < 2; j++) {
            int n = wc*16 + j*8 + cp2;
            size_t idx = ((size_t)bh*Tt + m)*Dd + n;
            *(float2*)&yp[idx]        = make_float2(acc[i][j][0], acc[i][j][1]);
            *(float2*)&yp[idx + 8*Dd] = make_float2(acc[i][j][2], acc[i][j][3]);
        }
    }
}

// ---------------------------------------------------------------------------
// ycomb: y = p0 + p1, split to bf16 hi/lo planes
// ---------------------------------------------------------------------------
__global__ __launch_bounds__(256) void ycomb_kernel()
{
    size_t i4 = (size_t)blockIdx.x * 256 + threadIdx.x;
    float4 a = ((const float4*)g_y_p0)[i4];
    float4 b = ((const float4*)g_y_p1)[i4];
    a.x += b.x; a.y += b.y; a.z += b.z; a.w += b.w;
    uint2 hi, lo;
    split4(a, hi, lo);
    ((uint2*)g_y_hi)[i4] = hi;
    ((uint2*)g_y_lo)[i4] = lo;
}

// ---------------------------------------------------------------------------
// output projection (tensor): y = yatt @ Wp^T + bp.
// Single-buffered smem, occupancy 2 (one wave).
// ---------------------------------------------------------------------------
__global__ __launch_bounds__(256, 2) void proj_kernel(
    const float* __restrict__ bp, float* __restrict__ y)
{
    extern __shared__ char dsm[];
    const uint32_t sb = smem_u32(dsm);
    const int t = threadIdx.x, lane = t & 31, w = t >> 5, wr = w >> 2, wc = w & 3;
    const int m0 = blockIdx.y * 128, n0 = blockIdx.x * 128;

    const int row = t >> 1, hf = t & 1;
    const int mrow = m0 + row, b_ = mrow >> 11, t_ = mrow & (Tt - 1);
    const __nv_bfloat16* bh = g_w_hi + (size_t)3*589824 + (size_t)(n0+row)*768 + hf*32;
    const __nv_bfloat16* bl = g_w_lo + (size_t)3*589824 + (size_t)(n0+row)*768 + hf*32;
    const uint32_t doff = (uint32_t)(row*144 + hf*64);

    float acc[4][4][4] = {};
    for (int c = 0; c < 12; c++) {
        issue4(sb + doff,
               g_y_hi + (((size_t)(b_*Hh + c))*Tt + t_)*Dd + hf*32,
               g_y_lo + (((size_t)(b_*Hh + c))*Tt + t_)*Dd + hf*32,
               bh + c*64, bl + c*64);
        cp_wait0();
        __syncthreads();
        consume_128x128(sb, sb+18432, sb+36864, sb+55296, wr, wc, lane, acc);
        __syncthreads();
    }
    const int r0 = lane >> 2, cp2 = (lane & 3)*2;
    #pragma unroll
    for (int i = 0; i < 4; i++) {
        int m = m0 + wr*64 + i*16 + r0;
        #pragma unroll
        for (int j = 0; j < 4; j++) {
            int n = n0 + wc*32 + j*8 + cp2;
            float2 bv = *(const float2*)&bp[n];
            *(float2*)&y[(size_t)m*Cc + n] =
                make_float2(acc[i][j][0] + bv.x, acc[i][j][1] + bv.y);
            *(float2*)&y[(size_t)(m+8)*Cc + n] =
                make_float2(acc[i][j][2] + bv.x, acc[i][j][3] + bv.y);
        }
    }
}

// ---------------------------------------------------------------------------
extern "C" void kernel_launch(void* const* d_in, const int* in_sizes, int n_in,
                              void* d_out, int out_size)
{
    (void)in_sizes; (void)n_in; (void)out_size;
    const float* x  = (const float*)d_in[0];
    const float* Wq = (const float*)d_in[1];
    const float* Wk = (const float*)d_in[2];
    const float* Wv = (const float*)d_in[3];
    const float* Wp = (const float*)d_in[4];
    const float* bp = (const float*)d_in[5];
    const float* rb = (const float*)d_in[6];
    float* y   = (float*)d_out;
    float* att = y + (size_t)Bb * Tt * Cc;

    static int inited = 0;
    if (!inited) {
        cudaFuncSetAttribute(qkv_kernel,    cudaFuncAttributeMaxDynamicSharedMemorySize, GBUF);
        cudaFuncSetAttribute(logits_kernel, cudaFuncAttributeMaxDynamicSharedMemorySize, GBUF);
        cudaFuncSetAttribute(av_kernel,     cudaFuncAttributeMaxDynamicSharedMemorySize, AV3_SMEM);
        cudaFuncSetAttribute(proj_kernel,   cudaFuncAttributeMaxDynamicSharedMemorySize, GBUF);
        inited = 1;
    }

    prep_kernel   <<<3072 + 4*576, 256>>>(x, Wq, Wk, Wv, Wp);
    qkv_kernel    <<<dim3(6, 32, 3), 256, GBUF>>>();
    rope_prep     <<<128, 256>>>();
    rope_kernel   <<<NBH*Tt*8/256, 256>>>();
    vT_kernel     <<<dim3(64, 2, NBH), 256>>>();
    logits_kernel <<<dim3(16, 16, NBH), 256, GBUF>>>(rb, att);
    softmax_kernel<<<NBH*Tt, 256>>>(att);
    av_kernel     <<<dim3(16, NBH, 2), 256, AV3_SMEM>>>(att);
    ycomb_kernel  <<<NBH*Tt*Dd/1024, 256>>>();
    proj_kernel   <<<dim3(6, 32), 256, GBUF>>>(bp, y);
}